// round 14
// baseline (speedup 1.0000x reference)
#include <cuda_runtime.h>
#include <cuda_fp16.h>
#include <cstdint>

// R14: warp-local f16 MLP, M=32 voxels/warp (two 16-row strips). Every weight
// B-frag lds128 feeds 4 MMAs (2 n-tiles x 2 strips) -> per-voxel crossbar halved.
// 2 CTAs/SM (128 regs), balanced persistent grid.

#define SP     262144
#define TB     256
#define GRID   296
#define NTILES 2048      // 524288 voxels / 256 per CTA-tile

// smem byte offsets
#define O_W2T  0         // 2048 entries * 16 B (sx<8, tp<8, lane)
#define O_W3T  32768     // 1024 * 16 (sx<8, tp<4, lane)
#define O_W1T  49152     // 256 * 8 (f16 k8 frags)
#define O_B1H  51200     // 64 * 4
#define O_B2H  51456     // 64 * 4
#define O_B3H  51712     // 32 * 4
#define O_W4H  51840     // 96 * 4  (c*32 + p)
#define O_B4   52224     // 3 f32 (+pad)
#define O_LZ   52240     // 256 rows * 3 f32 lorentz stash = 3072
#define SMEM_BYTES 55312

#define MMAH16(c0, c1, a0, a1, a2, a3, b0, b1) asm volatile( \
    "mma.sync.aligned.m16n8k16.row.col.f16.f16.f16.f16 " \
    "{%0,%1}, {%2,%3,%4,%5}, {%6,%7}, {%0,%1};" \
    : "+r"(c0), "+r"(c1) \
    : "r"(a0), "r"(a1), "r"(a2), "r"(a3), "r"(b0), "r"(b1))

#define MMAH8(c0, c1, a0, a1, b0) asm volatile( \
    "mma.sync.aligned.m16n8k8.row.col.f16.f16.f16.f16 " \
    "{%0,%1}, {%2,%3}, {%4}, {%0,%1};" \
    : "+r"(c0), "+r"(c1) : "r"(a0), "r"(a1), "r"(b0))

__device__ __forceinline__ uint32_t smem_u32(const void* p) {
    uint32_t a;
    asm("{ .reg .u64 t; cvta.to.shared.u64 t, %1; cvt.u32.u64 %0, t; }" : "=r"(a) : "l"(p));
    return a;
}
__device__ __forceinline__ uint32_t lds32(uint32_t a) {
    uint32_t v; asm volatile("ld.shared.b32 %0, [%1];" : "=r"(v) : "r"(a)); return v;
}
__device__ __forceinline__ uint2 lds64(uint32_t a) {
    uint2 v; asm volatile("ld.shared.v2.b32 {%0,%1}, [%2];" : "=r"(v.x), "=r"(v.y) : "r"(a)); return v;
}
__device__ __forceinline__ uint4 lds128(uint32_t a) {
    uint4 v;
    asm volatile("ld.shared.v4.b32 {%0,%1,%2,%3}, [%4];"
                 : "=r"(v.x), "=r"(v.y), "=r"(v.z), "=r"(v.w) : "r"(a));
    return v;
}
__device__ __forceinline__ uint32_t packh(float a, float b) {
    __half2 h = __floats2half2_rn(a, b);
    return *(uint32_t*)&h;
}
// bias-add + gelu(tanh) on packed f16x2
__device__ __forceinline__ uint32_t gb(uint32_t cu, uint32_t bu) {
    __half2 x = __hadd2(*(__half2*)&cu, *(__half2*)&bu);
    const __half2 c0 = __float2half2_rn(0.7978845608f);
    const __half2 c1 = __float2half2_rn(0.03567740814f);
    __half2 u = __hmul2(x, x);
    __half2 z = __hmul2(x, __hfma2(u, c1, c0));
    uint32_t zi = *(uint32_t*)&z, ti;
    asm("tanh.approx.f16x2 %0, %1;" : "=r"(ti) : "r"(zi));
    __half2 t = *(__half2*)&ti;
    __half2 hh = __hmul2(x, __float2half2_rn(0.5f));
    __half2 g = __hfma2(hh, t, hh);
    return *(uint32_t*)&g;
}

__global__ void __launch_bounds__(TB, 2)
mhd_m32(const float* __restrict__ flow, const float* __restrict__ Bf,
        const float* __restrict__ W1, const float* __restrict__ b1,
        const float* __restrict__ W2, const float* __restrict__ b2,
        const float* __restrict__ W3, const float* __restrict__ b3,
        const float* __restrict__ W4, const float* __restrict__ b4,
        float* __restrict__ out)
{
    extern __shared__ char smc[];
    const int tid  = threadIdx.x;
    const int wid  = tid >> 5;
    const int lane = tid & 31;
    const int q    = lane & 3;
    const int rsub = lane >> 2;
    const uint32_t smb = smem_u32(smc);

    // ---------------- stage weight B-fragment tables (once per CTA) ----------------
    for (int e = tid; e < 2048; e += TB) {      // W2T
        int l = e & 31, tp = (e >> 5) & 7, sx = e >> 8;
        int n0 = (2 * tp) * 8 + (l >> 2), n1 = n0 + 8;
        int k0 = sx * 16 + (l & 3) * 2;
        uint4 v;
        v.x = packh(W2[k0 * 128 + n0],       W2[(k0 + 1) * 128 + n0]);
        v.y = packh(W2[(k0 + 8) * 128 + n0], W2[(k0 + 9) * 128 + n0]);
        v.z = packh(W2[k0 * 128 + n1],       W2[(k0 + 1) * 128 + n1]);
        v.w = packh(W2[(k0 + 8) * 128 + n1], W2[(k0 + 9) * 128 + n1]);
        *(uint4*)(smc + O_W2T + e * 16) = v;
    }
    for (int e = tid; e < 1024; e += TB) {      // W3T
        int l = e & 31, tp = (e >> 5) & 3, sx = e >> 7;
        int n0 = (2 * tp) * 8 + (l >> 2), n1 = n0 + 8;
        int k0 = sx * 16 + (l & 3) * 2;
        uint4 v;
        v.x = packh(W3[k0 * 64 + n0],       W3[(k0 + 1) * 64 + n0]);
        v.y = packh(W3[(k0 + 8) * 64 + n0], W3[(k0 + 9) * 64 + n0]);
        v.z = packh(W3[k0 * 64 + n1],       W3[(k0 + 1) * 64 + n1]);
        v.w = packh(W3[(k0 + 8) * 64 + n1], W3[(k0 + 9) * 64 + n1]);
        *(uint4*)(smc + O_W3T + e * 16) = v;
    }
    for (int e = tid; e < 256; e += TB) {       // W1T (k>=6 zero)
        int l = e & 31, tp = e >> 5;
        int n0 = (2 * tp) * 8 + (l >> 2), n1 = n0 + 8;
        int k0 = (l & 3) * 2;
        float a0 = (k0 < 6) ? W1[k0 * 128 + n0] : 0.f;
        float a1 = (k0 + 1 < 6) ? W1[(k0 + 1) * 128 + n0] : 0.f;
        float a2 = (k0 < 6) ? W1[k0 * 128 + n1] : 0.f;
        float a3 = (k0 + 1 < 6) ? W1[(k0 + 1) * 128 + n1] : 0.f;
        uint2 v; v.x = packh(a0, a1); v.y = packh(a2, a3);
        *(uint2*)(smc + O_W1T + e * 8) = v;
    }
    for (int i = tid; i < 64; i += TB)
        *(uint32_t*)(smc + O_B1H + i * 4) = packh(b1[(i >> 2) * 8 + (i & 3) * 2],
                                                  b1[(i >> 2) * 8 + (i & 3) * 2 + 1]);
    for (int i = tid; i < 64; i += TB)
        *(uint32_t*)(smc + O_B2H + i * 4) = packh(b2[(i >> 2) * 8 + (i & 3) * 2],
                                                  b2[(i >> 2) * 8 + (i & 3) * 2 + 1]);
    for (int i = tid; i < 32; i += TB)
        *(uint32_t*)(smc + O_B3H + i * 4) = packh(b3[(i >> 2) * 8 + (i & 3) * 2],
                                                  b3[(i >> 2) * 8 + (i & 3) * 2 + 1]);
    for (int i = tid; i < 96; i += TB) {        // W4H[c*32+p] = {W4[2p][c], W4[2p+1][c]}
        int c = i >> 5, p = i & 31;
        *(uint32_t*)(smc + O_W4H + i * 4) = packh(W4[2 * p * 3 + c], W4[(2 * p + 1) * 3 + c]);
    }
    if (tid < 3) ((float*)(smc + O_B4))[tid] = b4[tid];
    __syncthreads();   // only block barrier

    // Balanced persistent loop over 2048 tiles of 256 voxels.
    for (int tile = blockIdx.x; tile < NTILES; tile += GRID) {
        const int vbase = tile * 256 + wid * 32;   // warp's 32-voxel strip pair
        const int b  = vbase >> 18;
        const int sb = vbase & (SP - 1);
        const float* Fb = flow + b * 3 * SP;
        const float* Bx = Bf + b * 3 * SP;
        const float* By = Bx + SP;
        const float* Bz = Bx + 2 * SP;

        // ---------------- P0: features into A-frags; lorentz (all 32 lanes) ----
        const int s0 = sb + rsub;                  // strip0 rows rsub / rsub+8
        uint32_t fa0, fa1, fa2, fa3;
        {
            float v00, v01, v10, v11, v20, v21, v30, v31;
            if (q == 0) {
                v00 = Fb[s0];      v01 = Fb[SP + s0];
                v10 = Fb[s0 + 8];  v11 = Fb[SP + s0 + 8];
                v20 = Fb[s0 + 16]; v21 = Fb[SP + s0 + 16];
                v30 = Fb[s0 + 24]; v31 = Fb[SP + s0 + 24];
            } else if (q == 1) {
                v00 = Fb[2 * SP + s0];      v01 = Bx[s0];
                v10 = Fb[2 * SP + s0 + 8];  v11 = Bx[s0 + 8];
                v20 = Fb[2 * SP + s0 + 16]; v21 = Bx[s0 + 16];
                v30 = Fb[2 * SP + s0 + 24]; v31 = Bx[s0 + 24];
            } else if (q == 2) {
                v00 = By[s0];      v01 = Bz[s0];
                v10 = By[s0 + 8];  v11 = Bz[s0 + 8];
                v20 = By[s0 + 16]; v21 = Bz[s0 + 16];
                v30 = By[s0 + 24]; v31 = Bz[s0 + 24];
            } else {
                v00 = v01 = v10 = v11 = v20 = v21 = v30 = v31 = 0.f;
            }
            fa0 = packh(v00, v01);
            fa1 = packh(v10, v11);
            fa2 = packh(v20, v21);
            fa3 = packh(v30, v31);
        }
        __syncwarp();          // prev tile's L4 reads of LZ rows complete
        {
            const int sm = sb + lane;              // one lorentz voxel per lane
            const int h = sm >> 12, w = (sm >> 6) & 63, d = sm & 63;
            const int H = h << 12, Wo = w << 6;
            const int hp = ((h + 1) & 63) << 12, hm = ((h - 1) & 63) << 12;
            const int wp = ((w + 1) & 63) << 6,  wm2 = ((w - 1) & 63) << 6;
            const int dp = (d + 1) & 63, dm = (d - 1) & 63;
            const float bx = Bx[H + Wo + d], by = By[H + Wo + d], bz = Bz[H + Wo + d];
            const float Jx = 0.5f * ((Bz[H + wp + d] - Bz[H + wm2 + d]) - (By[H + Wo + dp] - By[H + Wo + dm]));
            const float Jy = 0.5f * ((Bx[H + Wo + dp] - Bx[H + Wo + dm]) - (Bz[hp + Wo + d] - Bz[hm + Wo + d]));
            const float Jz = 0.5f * ((By[hp + Wo + d] - By[hm + Wo + d]) - (Bx[H + wp + d] - Bx[H + wm2 + d]));
            float* lz = (float*)(smc + O_LZ) + (wid * 32 + lane) * 3;
            lz[0] = (Jy * bz - Jz * by) * 2500.0f;
            lz[1] = (Jz * bx - Jx * bz) * 2500.0f;
            lz[2] = (Jx * by - Jy * bx) * 2500.0f;
        }

        uint32_t a0[16][2], a1[16][2];   // activations per strip

        // ---------------- L1: 6(->8) -> 128, k8 MMA, both strips ----------------
        {
            uint32_t c0[16][2], c1[16][2];
            #pragma unroll
            for (int t = 0; t < 16; t++) {
                c0[t][0] = 0u; c0[t][1] = 0u; c1[t][0] = 0u; c1[t][1] = 0u;
            }
            #pragma unroll
            for (int tp = 0; tp < 8; tp++) {
                uint2 B1f = lds64(smb + O_W1T + (uint32_t)(tp * 32 + lane) * 8);
                MMAH8(c0[2 * tp][0], c0[2 * tp][1], fa0, fa1, B1f.x);
                MMAH8(c1[2 * tp][0], c1[2 * tp][1], fa2, fa3, B1f.x);
                MMAH8(c0[2 * tp + 1][0], c0[2 * tp + 1][1], fa0, fa1, B1f.y);
                MMAH8(c1[2 * tp + 1][0], c1[2 * tp + 1][1], fa2, fa3, B1f.y);
            }
            #pragma unroll
            for (int t = 0; t < 16; t++) {
                uint32_t bb = lds32(smb + O_B1H + (uint32_t)(t * 4 + q) * 4);
                a0[t][0] = gb(c0[t][0], bb); a0[t][1] = gb(c0[t][1], bb);
                a1[t][0] = gb(c1[t][0], bb); a1[t][1] = gb(c1[t][1], bb);
            }
        }

        // ---------------- L2: 128 -> 128, each lds128 feeds 4 MMAs ----------------
        {
            uint32_t c0[16][2], c1[16][2];
            #pragma unroll
            for (int t = 0; t < 16; t++) {
                c0[t][0] = 0u; c0[t][1] = 0u; c1[t][0] = 0u; c1[t][1] = 0u;
            }
            #pragma unroll
            for (int sx = 0; sx < 8; sx++) {
                #pragma unroll
                for (int tp = 0; tp < 8; tp++) {
                    uint4 Bw = lds128(smb + O_W2T + (uint32_t)((sx * 8 + tp) * 32 + lane) * 16);
                    MMAH16(c0[2 * tp][0], c0[2 * tp][1],
                           a0[2 * sx][0], a0[2 * sx][1], a0[2 * sx + 1][0], a0[2 * sx + 1][1], Bw.x, Bw.y);
                    MMAH16(c1[2 * tp][0], c1[2 * tp][1],
                           a1[2 * sx][0], a1[2 * sx][1], a1[2 * sx + 1][0], a1[2 * sx + 1][1], Bw.x, Bw.y);
                    MMAH16(c0[2 * tp + 1][0], c0[2 * tp + 1][1],
                           a0[2 * sx][0], a0[2 * sx][1], a0[2 * sx + 1][0], a0[2 * sx + 1][1], Bw.z, Bw.w);
                    MMAH16(c1[2 * tp + 1][0], c1[2 * tp + 1][1],
                           a1[2 * sx][0], a1[2 * sx][1], a1[2 * sx + 1][0], a1[2 * sx + 1][1], Bw.z, Bw.w);
                }
            }
            #pragma unroll
            for (int t = 0; t < 16; t++) {
                uint32_t bb = lds32(smb + O_B2H + (uint32_t)(t * 4 + q) * 4);
                a0[t][0] = gb(c0[t][0], bb); a0[t][1] = gb(c0[t][1], bb);
                a1[t][0] = gb(c1[t][0], bb); a1[t][1] = gb(c1[t][1], bb);
            }
        }

        // ---------------- L3: 128 -> 64 ----------------
        uint32_t x30[8][2], x31[8][2];
        {
            #pragma unroll
            for (int t = 0; t < 8; t++) {
                x30[t][0] = 0u; x30[t][1] = 0u; x31[t][0] = 0u; x31[t][1] = 0u;
            }
            #pragma unroll
            for (int sx = 0; sx < 8; sx++) {
                #pragma unroll
                for (int tp = 0; tp < 4; tp++) {
                    uint4 Bw = lds128(smb + O_W3T + (uint32_t)((sx * 4 + tp) * 32 + lane) * 16);
                    MMAH16(x30[2 * tp][0], x30[2 * tp][1],
                           a0[2 * sx][0], a0[2 * sx][1], a0[2 * sx + 1][0], a0[2 * sx + 1][1], Bw.x, Bw.y);
                    MMAH16(x31[2 * tp][0], x31[2 * tp][1],
                           a1[2 * sx][0], a1[2 * sx][1], a1[2 * sx + 1][0], a1[2 * sx + 1][1], Bw.x, Bw.y);
                    MMAH16(x30[2 * tp + 1][0], x30[2 * tp + 1][1],
                           a0[2 * sx][0], a0[2 * sx][1], a0[2 * sx + 1][0], a0[2 * sx + 1][1], Bw.z, Bw.w);
                    MMAH16(x31[2 * tp + 1][0], x31[2 * tp + 1][1],
                           a1[2 * sx][0], a1[2 * sx][1], a1[2 * sx + 1][0], a1[2 * sx + 1][1], Bw.z, Bw.w);
                }
            }
            #pragma unroll
            for (int t = 0; t < 8; t++) {
                uint32_t bb = lds32(smb + O_B3H + (uint32_t)(t * 4 + q) * 4);
                x30[t][0] = gb(x30[t][0], bb); x30[t][1] = gb(x30[t][1], bb);
                x31[t][0] = gb(x31[t][0], bb); x31[t][1] = gb(x31[t][1], bb);
            }
        }

        // ---------------- L4: 64 -> 3, both strips; W4 lds shared ----------------
        __half2 acc[4][3];   // [strip*2 + rowhalf][comp]
        #pragma unroll
        for (int r = 0; r < 4; r++)
            #pragma unroll
            for (int cc = 0; cc < 3; cc++) acc[r][cc] = __float2half2_rn(0.f);
        #pragma unroll
        for (int t = 0; t < 8; t++) {
            #pragma unroll
            for (int cc = 0; cc < 3; cc++) {
                uint32_t wu = lds32(smb + O_W4H + (uint32_t)(cc * 32 + t * 4 + q) * 4);
                __half2 wh = *(__half2*)&wu;
                acc[0][cc] = __hfma2(*(__half2*)&x30[t][0], wh, acc[0][cc]);
                acc[1][cc] = __hfma2(*(__half2*)&x30[t][1], wh, acc[1][cc]);
                acc[2][cc] = __hfma2(*(__half2*)&x31[t][0], wh, acc[2][cc]);
                acc[3][cc] = __hfma2(*(__half2*)&x31[t][1], wh, acc[3][cc]);
            }
        }
        float pe[4][3];
        #pragma unroll
        for (int r = 0; r < 4; r++)
            #pragma unroll
            for (int cc = 0; cc < 3; cc++) {
                float2 f = __half22float2(acc[r][cc]);
                float vv = f.x + f.y;
                vv += __shfl_xor_sync(0xffffffffu, vv, 1);
                vv += __shfl_xor_sync(0xffffffffu, vv, 2);
                pe[r][cc] = vv + ((const float*)(smc + O_B4))[cc];
            }
        __syncwarp();          // LZ stores visible warp-wide
        if (q < 3) {
            const float* LZp = (const float*)(smc + O_LZ) + (wid * 32 + rsub) * 3 + q;
            float* ob = out + b * 3 * SP + q * SP;
            ob[s0]      = LZp[0]      + 0.1f * pe[0][q];
            ob[s0 + 8]  = LZp[8 * 3]  + 0.1f * pe[1][q];
            ob[s0 + 16] = LZp[16 * 3] + 0.1f * pe[2][q];
            ob[s0 + 24] = LZp[24 * 3] + 0.1f * pe[3][q];
        }
    }
}

extern "C" void kernel_launch(void* const* d_in, const int* in_sizes, int n_in,
                              void* d_out, int out_size)
{
    (void)in_sizes; (void)n_in; (void)out_size;
    cudaFuncSetAttribute(mhd_m32, cudaFuncAttributeMaxDynamicSharedMemorySize, SMEM_BYTES);
    mhd_m32<<<GRID, TB, SMEM_BYTES>>>(
        (const float*)d_in[0], (const float*)d_in[1], (const float*)d_in[2],
        (const float*)d_in[3], (const float*)d_in[4], (const float*)d_in[5],
        (const float*)d_in[6], (const float*)d_in[7], (const float*)d_in[8],
        (const float*)d_in[9], (float*)d_out);
}

// round 15
// speedup vs baseline: 1.0917x; 1.0917x over previous
#include <cuda_runtime.h>
#include <cuda_fp16.h>
#include <cstdint>

// R15 = R13 inner code (warp-local f16 MLP, M=16/warp, 3 CTAs/SM) with
// GRID=456 (=152 SMs x 3): uniform 3 CTAs/SM and ~uniform 9 tiles/CTA.

#define SP    262144
#define TB    256
#define GRID  456
#define NTILES 4096      // 524288 voxels / 128

// smem byte offsets
#define O_W2T  0         // 2048 entries * 16 B (sx<8, tp<8, lane)
#define O_W3T  32768     // 1024 * 16 (sx<8, tp<4, lane)
#define O_W1T  49152     // 256 * 8 (f16 k8 frags)
#define O_B1H  51200     // 64 * 4
#define O_B2H  51456     // 64 * 4
#define O_B3H  51712     // 32 * 4
#define O_W4H  51840     // 96 * 4  (c*32 + p)
#define O_B4   52224     // 3 f32 (+pad)
#define O_LZ   52240     // 128 rows * 3 f32 (warp-private lorentz stash)
#define SMEM_BYTES 53776

#define MMAH16(c0, c1, a0, a1, a2, a3, b0, b1) asm volatile( \
    "mma.sync.aligned.m16n8k16.row.col.f16.f16.f16.f16 " \
    "{%0,%1}, {%2,%3,%4,%5}, {%6,%7}, {%0,%1};" \
    : "+r"(c0), "+r"(c1) \
    : "r"(a0), "r"(a1), "r"(a2), "r"(a3), "r"(b0), "r"(b1))

#define MMAH8(c0, c1, a0, a1, b0) asm volatile( \
    "mma.sync.aligned.m16n8k8.row.col.f16.f16.f16.f16 " \
    "{%0,%1}, {%2,%3}, {%4}, {%0,%1};" \
    : "+r"(c0), "+r"(c1) : "r"(a0), "r"(a1), "r"(b0))

__device__ __forceinline__ uint32_t smem_u32(const void* p) {
    uint32_t a;
    asm("{ .reg .u64 t; cvta.to.shared.u64 t, %1; cvt.u32.u64 %0, t; }" : "=r"(a) : "l"(p));
    return a;
}
__device__ __forceinline__ uint32_t lds32(uint32_t a) {
    uint32_t v; asm volatile("ld.shared.b32 %0, [%1];" : "=r"(v) : "r"(a)); return v;
}
__device__ __forceinline__ uint2 lds64(uint32_t a) {
    uint2 v; asm volatile("ld.shared.v2.b32 {%0,%1}, [%2];" : "=r"(v.x), "=r"(v.y) : "r"(a)); return v;
}
__device__ __forceinline__ uint4 lds128(uint32_t a) {
    uint4 v;
    asm volatile("ld.shared.v4.b32 {%0,%1,%2,%3}, [%4];"
                 : "=r"(v.x), "=r"(v.y), "=r"(v.z), "=r"(v.w) : "r"(a));
    return v;
}
__device__ __forceinline__ uint32_t packh(float a, float b) {
    __half2 h = __floats2half2_rn(a, b);
    return *(uint32_t*)&h;
}
// bias-add + gelu(tanh) on packed f16x2
__device__ __forceinline__ uint32_t gb(uint32_t cu, uint32_t bu) {
    __half2 x = __hadd2(*(__half2*)&cu, *(__half2*)&bu);
    const __half2 c0 = __float2half2_rn(0.7978845608f);
    const __half2 c1 = __float2half2_rn(0.03567740814f);
    __half2 u = __hmul2(x, x);
    __half2 z = __hmul2(x, __hfma2(u, c1, c0));
    uint32_t zi = *(uint32_t*)&z, ti;
    asm("tanh.approx.f16x2 %0, %1;" : "=r"(ti) : "r"(zi));
    __half2 t = *(__half2*)&ti;
    __half2 hh = __hmul2(x, __float2half2_rn(0.5f));
    __half2 g = __hfma2(hh, t, hh);
    return *(uint32_t*)&g;
}

__global__ void __launch_bounds__(TB, 3)
mhd_wl5(const float* __restrict__ flow, const float* __restrict__ Bf,
        const float* __restrict__ W1, const float* __restrict__ b1,
        const float* __restrict__ W2, const float* __restrict__ b2,
        const float* __restrict__ W3, const float* __restrict__ b3,
        const float* __restrict__ W4, const float* __restrict__ b4,
        float* __restrict__ out)
{
    extern __shared__ char smc[];
    const int tid  = threadIdx.x;
    const int wid  = tid >> 5;
    const int lane = tid & 31;
    const int q    = lane & 3;
    const int rsub = lane >> 2;
    const uint32_t smb = smem_u32(smc);

    // ---------------- stage weight B-fragment tables (once per CTA) ----------------
    for (int e = tid; e < 2048; e += TB) {      // W2T
        int l = e & 31, tp = (e >> 5) & 7, sx = e >> 8;
        int n0 = (2 * tp) * 8 + (l >> 2), n1 = n0 + 8;
        int k0 = sx * 16 + (l & 3) * 2;
        uint4 v;
        v.x = packh(W2[k0 * 128 + n0],       W2[(k0 + 1) * 128 + n0]);
        v.y = packh(W2[(k0 + 8) * 128 + n0], W2[(k0 + 9) * 128 + n0]);
        v.z = packh(W2[k0 * 128 + n1],       W2[(k0 + 1) * 128 + n1]);
        v.w = packh(W2[(k0 + 8) * 128 + n1], W2[(k0 + 9) * 128 + n1]);
        *(uint4*)(smc + O_W2T + e * 16) = v;
    }
    for (int e = tid; e < 1024; e += TB) {      // W3T
        int l = e & 31, tp = (e >> 5) & 3, sx = e >> 7;
        int n0 = (2 * tp) * 8 + (l >> 2), n1 = n0 + 8;
        int k0 = sx * 16 + (l & 3) * 2;
        uint4 v;
        v.x = packh(W3[k0 * 64 + n0],       W3[(k0 + 1) * 64 + n0]);
        v.y = packh(W3[(k0 + 8) * 64 + n0], W3[(k0 + 9) * 64 + n0]);
        v.z = packh(W3[k0 * 64 + n1],       W3[(k0 + 1) * 64 + n1]);
        v.w = packh(W3[(k0 + 8) * 64 + n1], W3[(k0 + 9) * 64 + n1]);
        *(uint4*)(smc + O_W3T + e * 16) = v;
    }
    for (int e = tid; e < 256; e += TB) {       // W1T (k>=6 zero)
        int l = e & 31, tp = e >> 5;
        int n0 = (2 * tp) * 8 + (l >> 2), n1 = n0 + 8;
        int k0 = (l & 3) * 2;
        float a0 = (k0 < 6) ? W1[k0 * 128 + n0] : 0.f;
        float a1 = (k0 + 1 < 6) ? W1[(k0 + 1) * 128 + n0] : 0.f;
        float a2 = (k0 < 6) ? W1[k0 * 128 + n1] : 0.f;
        float a3 = (k0 + 1 < 6) ? W1[(k0 + 1) * 128 + n1] : 0.f;
        uint2 v; v.x = packh(a0, a1); v.y = packh(a2, a3);
        *(uint2*)(smc + O_W1T + e * 8) = v;
    }
    for (int i = tid; i < 64; i += TB)
        *(uint32_t*)(smc + O_B1H + i * 4) = packh(b1[(i >> 2) * 8 + (i & 3) * 2],
                                                  b1[(i >> 2) * 8 + (i & 3) * 2 + 1]);
    for (int i = tid; i < 64; i += TB)
        *(uint32_t*)(smc + O_B2H + i * 4) = packh(b2[(i >> 2) * 8 + (i & 3) * 2],
                                                  b2[(i >> 2) * 8 + (i & 3) * 2 + 1]);
    for (int i = tid; i < 32; i += TB)
        *(uint32_t*)(smc + O_B3H + i * 4) = packh(b3[(i >> 2) * 8 + (i & 3) * 2],
                                                  b3[(i >> 2) * 8 + (i & 3) * 2 + 1]);
    for (int i = tid; i < 96; i += TB) {        // W4H[c*32+p] = {W4[2p][c], W4[2p+1][c]}
        int c = i >> 5, p = i & 31;
        *(uint32_t*)(smc + O_W4H + i * 4) = packh(W4[2 * p * 3 + c], W4[(2 * p + 1) * 3 + c]);
    }
    if (tid < 3) ((float*)(smc + O_B4))[tid] = b4[tid];
    __syncthreads();   // only block barrier in the kernel

    // Balanced persistent loop: 456 CTAs (3 per SM on 152 SMs), tiles strided.
    for (int tile = blockIdx.x; tile < NTILES; tile += GRID) {
        const int vbase = tile * 128 + wid * 16;   // warp's 16-voxel strip
        const int b  = vbase >> 18;
        const int sb = vbase & (SP - 1);
        const float* Fb = flow + b * 3 * SP;
        const float* Bx = Bf + b * 3 * SP;
        const float* By = Bx + SP;
        const float* Bz = Bx + 2 * SP;

        // ---------------- P0: features into A-frags; lorentz -> smem stash ----
        const int s0 = sb + rsub, s1 = s0 + 8;
        uint32_t fa0, fa1;
        {
            float l0, h0, l1, h1;
            if (q == 0)      { l0 = Fb[s0]; h0 = Fb[SP + s0]; l1 = Fb[s1]; h1 = Fb[SP + s1]; }
            else if (q == 1) { l0 = Fb[2 * SP + s0]; h0 = Bx[s0]; l1 = Fb[2 * SP + s1]; h1 = Bx[s1]; }
            else if (q == 2) { l0 = By[s0]; h0 = Bz[s0]; l1 = By[s1]; h1 = Bz[s1]; }
            else             { l0 = h0 = l1 = h1 = 0.f; }
            fa0 = packh(l0, h0);
            fa1 = packh(l1, h1);
        }
        __syncwarp();          // prev tile's L4 reads of LZ rows complete
        if (lane < 16) {
            const int sm = sb + lane;
            const int h = sm >> 12, w = (sm >> 6) & 63, d = sm & 63;
            const int H = h << 12, Wo = w << 6;
            const int hp = ((h + 1) & 63) << 12, hm = ((h - 1) & 63) << 12;
            const int wp = ((w + 1) & 63) << 6,  wm2 = ((w - 1) & 63) << 6;
            const int dp = (d + 1) & 63, dm = (d - 1) & 63;
            const float bx = Bx[H + Wo + d], by = By[H + Wo + d], bz = Bz[H + Wo + d];
            const float Jx = 0.5f * ((Bz[H + wp + d] - Bz[H + wm2 + d]) - (By[H + Wo + dp] - By[H + Wo + dm]));
            const float Jy = 0.5f * ((Bx[H + Wo + dp] - Bx[H + Wo + dm]) - (Bz[hp + Wo + d] - Bz[hm + Wo + d]));
            const float Jz = 0.5f * ((By[hp + Wo + d] - By[hm + Wo + d]) - (Bx[H + wp + d] - Bx[H + wm2 + d]));
            float* lz = (float*)(smc + O_LZ) + (wid * 16 + lane) * 3;
            lz[0] = (Jy * bz - Jz * by) * 2500.0f;
            lz[1] = (Jz * bx - Jx * bz) * 2500.0f;
            lz[2] = (Jx * by - Jy * bx) * 2500.0f;
        }

        uint32_t a[16][2];    // activations (A-frags / gelu'd C-frags)
        uint32_t c[16][2];    // accumulators

        // ---------------- L1: 6(->8) -> 128, k8 MMA ----------------
        #pragma unroll
        for (int t = 0; t < 16; t++) { c[t][0] = 0u; c[t][1] = 0u; }
        #pragma unroll
        for (int tp = 0; tp < 8; tp++) {
            uint2 B1f = lds64(smb + O_W1T + (uint32_t)(tp * 32 + lane) * 8);
            MMAH8(c[2 * tp][0], c[2 * tp][1], fa0, fa1, B1f.x);
            MMAH8(c[2 * tp + 1][0], c[2 * tp + 1][1], fa0, fa1, B1f.y);
        }
        #pragma unroll
        for (int t = 0; t < 16; t++) {
            uint32_t bb = lds32(smb + O_B1H + (uint32_t)(t * 4 + q) * 4);
            a[t][0] = gb(c[t][0], bb);
            a[t][1] = gb(c[t][1], bb);
        }

        // ---------------- L2: 128 -> 128 ----------------
        #pragma unroll
        for (int t = 0; t < 16; t++) { c[t][0] = 0u; c[t][1] = 0u; }
        #pragma unroll
        for (int sx = 0; sx < 8; sx++) {
            const uint32_t a0 = a[2 * sx][0], a1 = a[2 * sx][1];
            const uint32_t a2 = a[2 * sx + 1][0], a3 = a[2 * sx + 1][1];
            #pragma unroll
            for (int tp = 0; tp < 8; tp++) {
                uint4 Bf2 = lds128(smb + O_W2T + (uint32_t)((sx * 8 + tp) * 32 + lane) * 16);
                MMAH16(c[2 * tp][0], c[2 * tp][1], a0, a1, a2, a3, Bf2.x, Bf2.y);
                MMAH16(c[2 * tp + 1][0], c[2 * tp + 1][1], a0, a1, a2, a3, Bf2.z, Bf2.w);
            }
        }
        #pragma unroll
        for (int t = 0; t < 16; t++) {
            uint32_t bb = lds32(smb + O_B2H + (uint32_t)(t * 4 + q) * 4);
            a[t][0] = gb(c[t][0], bb);
            a[t][1] = gb(c[t][1], bb);
        }

        // ---------------- L3: 128 -> 64 ----------------
        uint32_t c3[8][2];
        #pragma unroll
        for (int t = 0; t < 8; t++) { c3[t][0] = 0u; c3[t][1] = 0u; }
        #pragma unroll
        for (int sx = 0; sx < 8; sx++) {
            const uint32_t a0 = a[2 * sx][0], a1 = a[2 * sx][1];
            const uint32_t a2 = a[2 * sx + 1][0], a3 = a[2 * sx + 1][1];
            #pragma unroll
            for (int tp = 0; tp < 4; tp++) {
                uint4 Bf3 = lds128(smb + O_W3T + (uint32_t)((sx * 4 + tp) * 32 + lane) * 16);
                MMAH16(c3[2 * tp][0], c3[2 * tp][1], a0, a1, a2, a3, Bf3.x, Bf3.y);
                MMAH16(c3[2 * tp + 1][0], c3[2 * tp + 1][1], a0, a1, a2, a3, Bf3.z, Bf3.w);
            }
        }
        #pragma unroll
        for (int t = 0; t < 8; t++) {
            uint32_t bb = lds32(smb + O_B3H + (uint32_t)(t * 4 + q) * 4);
            c3[t][0] = gb(c3[t][0], bb);    // x3 in place
            c3[t][1] = gb(c3[t][1], bb);
        }

        // ---------------- L4: 64 -> 3 (hfma2 dot + quad butterfly) ----------------
        __half2 acc[2][3];
        #pragma unroll
        for (int r = 0; r < 2; r++)
            #pragma unroll
            for (int cc = 0; cc < 3; cc++) acc[r][cc] = __float2half2_rn(0.f);
        #pragma unroll
        for (int t = 0; t < 8; t++) {
            #pragma unroll
            for (int cc = 0; cc < 3; cc++) {
                uint32_t wu = lds32(smb + O_W4H + (uint32_t)(cc * 32 + t * 4 + q) * 4);
                __half2 wh = *(__half2*)&wu;
                acc[0][cc] = __hfma2(*(__half2*)&c3[t][0], wh, acc[0][cc]);
                acc[1][cc] = __hfma2(*(__half2*)&c3[t][1], wh, acc[1][cc]);
            }
        }
        float pe[2][3];
        #pragma unroll
        for (int r = 0; r < 2; r++)
            #pragma unroll
            for (int cc = 0; cc < 3; cc++) {
                float2 f = __half22float2(acc[r][cc]);
                float vv = f.x + f.y;
                vv += __shfl_xor_sync(0xffffffffu, vv, 1);
                vv += __shfl_xor_sync(0xffffffffu, vv, 2);
                pe[r][cc] = vv + ((const float*)(smc + O_B4))[cc];
            }
        __syncwarp();          // LZ stores (lanes 0-15) visible to all lanes
        if (q < 3) {
            const float L0 = ((const float*)(smc + O_LZ))[(wid * 16 + rsub) * 3 + q];
            const float L1 = ((const float*)(smc + O_LZ))[(wid * 16 + rsub + 8) * 3 + q];
            float* ob = out + b * 3 * SP + q * SP;
            ob[s0] = L0 + 0.1f * pe[0][q];
            ob[s1] = L1 + 0.1f * pe[1][q];
        }
    }
}

extern "C" void kernel_launch(void* const* d_in, const int* in_sizes, int n_in,
                              void* d_out, int out_size)
{
    (void)in_sizes; (void)n_in; (void)out_size;
    cudaFuncSetAttribute(mhd_wl5, cudaFuncAttributeMaxDynamicSharedMemorySize, SMEM_BYTES);
    mhd_wl5<<<GRID, TB, SMEM_BYTES>>>(
        (const float*)d_in[0], (const float*)d_in[1], (const float*)d_in[2],
        (const float*)d_in[3], (const float*)d_in[4], (const float*)d_in[5],
        (const float*)d_in[6], (const float*)d_in[7], (const float*)d_in[8],
        (const float*)d_in[9], (float*)d_out);
}

// round 16
// speedup vs baseline: 1.1500x; 1.0535x over previous
#include <cuda_runtime.h>
#include <cuda_fp16.h>
#include <cstdint>

// R16 = R15 (warp-local f16 MLP, M=16/warp, 3 CTAs/SM, GRID=456) with cheaper
// gelu: sigmoid form x*sigma(1.702x)=0.5x(1+tanh(0.851x)) — 4 f16x2 ops + tanh.

#define SP    262144
#define TB    256
#define GRID  456
#define NTILES 4096      // 524288 voxels / 128

// smem byte offsets
#define O_W2T  0         // 2048 entries * 16 B (sx<8, tp<8, lane)
#define O_W3T  32768     // 1024 * 16 (sx<8, tp<4, lane)
#define O_W1T  49152     // 256 * 8 (f16 k8 frags)
#define O_B1H  51200     // 64 * 4
#define O_B2H  51456     // 64 * 4
#define O_B3H  51712     // 32 * 4
#define O_W4H  51840     // 96 * 4  (c*32 + p)
#define O_B4   52224     // 3 f32 (+pad)
#define O_LZ   52240     // 128 rows * 3 f32 (warp-private lorentz stash)
#define SMEM_BYTES 53776

#define MMAH16(c0, c1, a0, a1, a2, a3, b0, b1) asm volatile( \
    "mma.sync.aligned.m16n8k16.row.col.f16.f16.f16.f16 " \
    "{%0,%1}, {%2,%3,%4,%5}, {%6,%7}, {%0,%1};" \
    : "+r"(c0), "+r"(c1) \
    : "r"(a0), "r"(a1), "r"(a2), "r"(a3), "r"(b0), "r"(b1))

#define MMAH8(c0, c1, a0, a1, b0) asm volatile( \
    "mma.sync.aligned.m16n8k8.row.col.f16.f16.f16.f16 " \
    "{%0,%1}, {%2,%3}, {%4}, {%0,%1};" \
    : "+r"(c0), "+r"(c1) : "r"(a0), "r"(a1), "r"(b0))

__device__ __forceinline__ uint32_t smem_u32(const void* p) {
    uint32_t a;
    asm("{ .reg .u64 t; cvta.to.shared.u64 t, %1; cvt.u32.u64 %0, t; }" : "=r"(a) : "l"(p));
    return a;
}
__device__ __forceinline__ uint32_t lds32(uint32_t a) {
    uint32_t v; asm volatile("ld.shared.b32 %0, [%1];" : "=r"(v) : "r"(a)); return v;
}
__device__ __forceinline__ uint2 lds64(uint32_t a) {
    uint2 v; asm volatile("ld.shared.v2.b32 {%0,%1}, [%2];" : "=r"(v.x), "=r"(v.y) : "r"(a)); return v;
}
__device__ __forceinline__ uint4 lds128(uint32_t a) {
    uint4 v;
    asm volatile("ld.shared.v4.b32 {%0,%1,%2,%3}, [%4];"
                 : "=r"(v.x), "=r"(v.y), "=r"(v.z), "=r"(v.w) : "r"(a));
    return v;
}
__device__ __forceinline__ uint32_t packh(float a, float b) {
    __half2 h = __floats2half2_rn(a, b);
    return *(uint32_t*)&h;
}
// bias-add + gelu (sigmoid form) on packed f16x2:
// gelu(x) ~= 0.5*x*(1 + tanh(0.851*x))
__device__ __forceinline__ uint32_t gb(uint32_t cu, uint32_t bu) {
    __half2 x = __hadd2(*(__half2*)&cu, *(__half2*)&bu);
    __half2 z = __hmul2(x, __float2half2_rn(0.851f));
    uint32_t zi = *(uint32_t*)&z, ti;
    asm("tanh.approx.f16x2 %0, %1;" : "=r"(ti) : "r"(zi));
    __half2 t = *(__half2*)&ti;
    __half2 hh = __hmul2(x, __float2half2_rn(0.5f));
    __half2 g = __hfma2(hh, t, hh);
    return *(uint32_t*)&g;
}

__global__ void __launch_bounds__(TB, 3)
mhd_wl6(const float* __restrict__ flow, const float* __restrict__ Bf,
        const float* __restrict__ W1, const float* __restrict__ b1,
        const float* __restrict__ W2, const float* __restrict__ b2,
        const float* __restrict__ W3, const float* __restrict__ b3,
        const float* __restrict__ W4, const float* __restrict__ b4,
        float* __restrict__ out)
{
    extern __shared__ char smc[];
    const int tid  = threadIdx.x;
    const int wid  = tid >> 5;
    const int lane = tid & 31;
    const int q    = lane & 3;
    const int rsub = lane >> 2;
    const uint32_t smb = smem_u32(smc);

    // ---------------- stage weight B-fragment tables (once per CTA) ----------------
    for (int e = tid; e < 2048; e += TB) {      // W2T
        int l = e & 31, tp = (e >> 5) & 7, sx = e >> 8;
        int n0 = (2 * tp) * 8 + (l >> 2), n1 = n0 + 8;
        int k0 = sx * 16 + (l & 3) * 2;
        uint4 v;
        v.x = packh(W2[k0 * 128 + n0],       W2[(k0 + 1) * 128 + n0]);
        v.y = packh(W2[(k0 + 8) * 128 + n0], W2[(k0 + 9) * 128 + n0]);
        v.z = packh(W2[k0 * 128 + n1],       W2[(k0 + 1) * 128 + n1]);
        v.w = packh(W2[(k0 + 8) * 128 + n1], W2[(k0 + 9) * 128 + n1]);
        *(uint4*)(smc + O_W2T + e * 16) = v;
    }
    for (int e = tid; e < 1024; e += TB) {      // W3T
        int l = e & 31, tp = (e >> 5) & 3, sx = e >> 7;
        int n0 = (2 * tp) * 8 + (l >> 2), n1 = n0 + 8;
        int k0 = sx * 16 + (l & 3) * 2;
        uint4 v;
        v.x = packh(W3[k0 * 64 + n0],       W3[(k0 + 1) * 64 + n0]);
        v.y = packh(W3[(k0 + 8) * 64 + n0], W3[(k0 + 9) * 64 + n0]);
        v.z = packh(W3[k0 * 64 + n1],       W3[(k0 + 1) * 64 + n1]);
        v.w = packh(W3[(k0 + 8) * 64 + n1], W3[(k0 + 9) * 64 + n1]);
        *(uint4*)(smc + O_W3T + e * 16) = v;
    }
    for (int e = tid; e < 256; e += TB) {       // W1T (k>=6 zero)
        int l = e & 31, tp = e >> 5;
        int n0 = (2 * tp) * 8 + (l >> 2), n1 = n0 + 8;
        int k0 = (l & 3) * 2;
        float a0 = (k0 < 6) ? W1[k0 * 128 + n0] : 0.f;
        float a1 = (k0 + 1 < 6) ? W1[(k0 + 1) * 128 + n0] : 0.f;
        float a2 = (k0 < 6) ? W1[k0 * 128 + n1] : 0.f;
        float a3 = (k0 + 1 < 6) ? W1[(k0 + 1) * 128 + n1] : 0.f;
        uint2 v; v.x = packh(a0, a1); v.y = packh(a2, a3);
        *(uint2*)(smc + O_W1T + e * 8) = v;
    }
    for (int i = tid; i < 64; i += TB)
        *(uint32_t*)(smc + O_B1H + i * 4) = packh(b1[(i >> 2) * 8 + (i & 3) * 2],
                                                  b1[(i >> 2) * 8 + (i & 3) * 2 + 1]);
    for (int i = tid; i < 64; i += TB)
        *(uint32_t*)(smc + O_B2H + i * 4) = packh(b2[(i >> 2) * 8 + (i & 3) * 2],
                                                  b2[(i >> 2) * 8 + (i & 3) * 2 + 1]);
    for (int i = tid; i < 32; i += TB)
        *(uint32_t*)(smc + O_B3H + i * 4) = packh(b3[(i >> 2) * 8 + (i & 3) * 2],
                                                  b3[(i >> 2) * 8 + (i & 3) * 2 + 1]);
    for (int i = tid; i < 96; i += TB) {        // W4H[c*32+p] = {W4[2p][c], W4[2p+1][c]}
        int c = i >> 5, p = i & 31;
        *(uint32_t*)(smc + O_W4H + i * 4) = packh(W4[2 * p * 3 + c], W4[(2 * p + 1) * 3 + c]);
    }
    if (tid < 3) ((float*)(smc + O_B4))[tid] = b4[tid];
    __syncthreads();   // only block barrier in the kernel

    // Balanced persistent loop: 456 CTAs (3 per SM on 152 SMs), tiles strided.
    for (int tile = blockIdx.x; tile < NTILES; tile += GRID) {
        const int vbase = tile * 128 + wid * 16;   // warp's 16-voxel strip
        const int b  = vbase >> 18;
        const int sb = vbase & (SP - 1);
        const float* Fb = flow + b * 3 * SP;
        const float* Bx = Bf + b * 3 * SP;
        const float* By = Bx + SP;
        const float* Bz = Bx + 2 * SP;

        // ---------------- P0: features into A-frags; lorentz -> smem stash ----
        const int s0 = sb + rsub, s1 = s0 + 8;
        uint32_t fa0, fa1;
        {
            float l0, h0, l1, h1;
            if (q == 0)      { l0 = Fb[s0]; h0 = Fb[SP + s0]; l1 = Fb[s1]; h1 = Fb[SP + s1]; }
            else if (q == 1) { l0 = Fb[2 * SP + s0]; h0 = Bx[s0]; l1 = Fb[2 * SP + s1]; h1 = Bx[s1]; }
            else if (q == 2) { l0 = By[s0]; h0 = Bz[s0]; l1 = By[s1]; h1 = Bz[s1]; }
            else             { l0 = h0 = l1 = h1 = 0.f; }
            fa0 = packh(l0, h0);
            fa1 = packh(l1, h1);
        }
        __syncwarp();          // prev tile's L4 reads of LZ rows complete
        if (lane < 16) {
            const int sm = sb + lane;
            const int h = sm >> 12, w = (sm >> 6) & 63, d = sm & 63;
            const int H = h << 12, Wo = w << 6;
            const int hp = ((h + 1) & 63) << 12, hm = ((h - 1) & 63) << 12;
            const int wp = ((w + 1) & 63) << 6,  wm2 = ((w - 1) & 63) << 6;
            const int dp = (d + 1) & 63, dm = (d - 1) & 63;
            const float bx = Bx[H + Wo + d], by = By[H + Wo + d], bz = Bz[H + Wo + d];
            const float Jx = 0.5f * ((Bz[H + wp + d] - Bz[H + wm2 + d]) - (By[H + Wo + dp] - By[H + Wo + dm]));
            const float Jy = 0.5f * ((Bx[H + Wo + dp] - Bx[H + Wo + dm]) - (Bz[hp + Wo + d] - Bz[hm + Wo + d]));
            const float Jz = 0.5f * ((By[hp + Wo + d] - By[hm + Wo + d]) - (Bx[H + wp + d] - Bx[H + wm2 + d]));
            float* lz = (float*)(smc + O_LZ) + (wid * 16 + lane) * 3;
            lz[0] = (Jy * bz - Jz * by) * 2500.0f;
            lz[1] = (Jz * bx - Jx * bz) * 2500.0f;
            lz[2] = (Jx * by - Jy * bx) * 2500.0f;
        }

        uint32_t a[16][2];    // activations (A-frags / gelu'd C-frags)
        uint32_t c[16][2];    // accumulators

        // ---------------- L1: 6(->8) -> 128, k8 MMA ----------------
        #pragma unroll
        for (int t = 0; t < 16; t++) { c[t][0] = 0u; c[t][1] = 0u; }
        #pragma unroll
        for (int tp = 0; tp < 8; tp++) {
            uint2 B1f = lds64(smb + O_W1T + (uint32_t)(tp * 32 + lane) * 8);
            MMAH8(c[2 * tp][0], c[2 * tp][1], fa0, fa1, B1f.x);
            MMAH8(c[2 * tp + 1][0], c[2 * tp + 1][1], fa0, fa1, B1f.y);
        }
        #pragma unroll
        for (int t = 0; t < 16; t++) {
            uint32_t bb = lds32(smb + O_B1H + (uint32_t)(t * 4 + q) * 4);
            a[t][0] = gb(c[t][0], bb);
            a[t][1] = gb(c[t][1], bb);
        }

        // ---------------- L2: 128 -> 128 ----------------
        #pragma unroll
        for (int t = 0; t < 16; t++) { c[t][0] = 0u; c[t][1] = 0u; }
        #pragma unroll
        for (int sx = 0; sx < 8; sx++) {
            const uint32_t a0 = a[2 * sx][0], a1 = a[2 * sx][1];
            const uint32_t a2 = a[2 * sx + 1][0], a3 = a[2 * sx + 1][1];
            #pragma unroll
            for (int tp = 0; tp < 8; tp++) {
                uint4 Bf2 = lds128(smb + O_W2T + (uint32_t)((sx * 8 + tp) * 32 + lane) * 16);
                MMAH16(c[2 * tp][0], c[2 * tp][1], a0, a1, a2, a3, Bf2.x, Bf2.y);
                MMAH16(c[2 * tp + 1][0], c[2 * tp + 1][1], a0, a1, a2, a3, Bf2.z, Bf2.w);
            }
        }
        #pragma unroll
        for (int t = 0; t < 16; t++) {
            uint32_t bb = lds32(smb + O_B2H + (uint32_t)(t * 4 + q) * 4);
            a[t][0] = gb(c[t][0], bb);
            a[t][1] = gb(c[t][1], bb);
        }

        // ---------------- L3: 128 -> 64 ----------------
        uint32_t c3[8][2];
        #pragma unroll
        for (int t = 0; t < 8; t++) { c3[t][0] = 0u; c3[t][1] = 0u; }
        #pragma unroll
        for (int sx = 0; sx < 8; sx++) {
            const uint32_t a0 = a[2 * sx][0], a1 = a[2 * sx][1];
            const uint32_t a2 = a[2 * sx + 1][0], a3 = a[2 * sx + 1][1];
            #pragma unroll
            for (int tp = 0; tp < 4; tp++) {
                uint4 Bf3 = lds128(smb + O_W3T + (uint32_t)((sx * 4 + tp) * 32 + lane) * 16);
                MMAH16(c3[2 * tp][0], c3[2 * tp][1], a0, a1, a2, a3, Bf3.x, Bf3.y);
                MMAH16(c3[2 * tp + 1][0], c3[2 * tp + 1][1], a0, a1, a2, a3, Bf3.z, Bf3.w);
            }
        }
        #pragma unroll
        for (int t = 0; t < 8; t++) {
            uint32_t bb = lds32(smb + O_B3H + (uint32_t)(t * 4 + q) * 4);
            c3[t][0] = gb(c3[t][0], bb);    // x3 in place
            c3[t][1] = gb(c3[t][1], bb);
        }

        // ---------------- L4: 64 -> 3 (hfma2 dot + quad butterfly) ----------------
        __half2 acc[2][3];
        #pragma unroll
        for (int r = 0; r < 2; r++)
            #pragma unroll
            for (int cc = 0; cc < 3; cc++) acc[r][cc] = __float2half2_rn(0.f);
        #pragma unroll
        for (int t = 0; t < 8; t++) {
            #pragma unroll
            for (int cc = 0; cc < 3; cc++) {
                uint32_t wu = lds32(smb + O_W4H + (uint32_t)(cc * 32 + t * 4 + q) * 4);
                __half2 wh = *(__half2*)&wu;
                acc[0][cc] = __hfma2(*(__half2*)&c3[t][0], wh, acc[0][cc]);
                acc[1][cc] = __hfma2(*(__half2*)&c3[t][1], wh, acc[1][cc]);
            }
        }
        float pe[2][3];
        #pragma unroll
        for (int r = 0; r < 2; r++)
            #pragma unroll
            for (int cc = 0; cc < 3; cc++) {
                float2 f = __half22float2(acc[r][cc]);
                float vv = f.x + f.y;
                vv += __shfl_xor_sync(0xffffffffu, vv, 1);
                vv += __shfl_xor_sync(0xffffffffu, vv, 2);
                pe[r][cc] = vv + ((const float*)(smc + O_B4))[cc];
            }
        __syncwarp();          // LZ stores (lanes 0-15) visible to all lanes
        if (q < 3) {
            const float L0 = ((const float*)(smc + O_LZ))[(wid * 16 + rsub) * 3 + q];
            const float L1 = ((const float*)(smc + O_LZ))[(wid * 16 + rsub + 8) * 3 + q];
            float* ob = out + b * 3 * SP + q * SP;
            ob[s0] = L0 + 0.1f * pe[0][q];
            ob[s1] = L1 + 0.1f * pe[1][q];
        }
    }
}

extern "C" void kernel_launch(void* const* d_in, const int* in_sizes, int n_in,
                              void* d_out, int out_size)
{
    (void)in_sizes; (void)n_in; (void)out_size;
    cudaFuncSetAttribute(mhd_wl6, cudaFuncAttributeMaxDynamicSharedMemorySize, SMEM_BYTES);
    mhd_wl6<<<GRID, TB, SMEM_BYTES>>>(
        (const float*)d_in[0], (const float*)d_in[1], (const float*)d_in[2],
        (const float*)d_in[3], (const float*)d_in[4], (const float*)d_in[5],
        (const float*)d_in[6], (const float*)d_in[7], (const float*)d_in[8],
        (const float*)d_in[9], (float*)d_out);
}